// round 8
// baseline (speedup 1.0000x reference)
#include <cuda_runtime.h>
#include <math.h>

// Problem constants
#define NB   8192
#define NC   45
#define NL   21
#define NE   22
#define NCL  945          // NC*NL
#define NPAIR 462         // NE*NL
#define BATCH_PER_BLK 8
#define NBLK (NB / BATCH_PER_BLK)   // 1024

// ---------------- scratch (device globals; no allocation) ----------------
__device__ float g_gate[NB * NC];
__device__ float g_partial[NBLK * NC];
__device__ int   g_sel[NE];
__device__ int   g_c2e[NC];
__device__ float g_a1[NE], g_a3[NE], g_c1[NE], g_c0[NE];

// floor(p/21) for p in [0, 945): (p*6242)>>17  (verified exact on this range)
__device__ __forceinline__ int div21(int p) { return (int)(((unsigned)(p * 6242)) >> 17); }

// ============================ Kernel A: gating ============================
// One warp per batch, 8 batches per 256-thread block.
__global__ __launch_bounds__(256) void gate_kernel(
    const float* __restrict__ x,
    const float* __restrict__ gc_w, const float* __restrict__ gc_b,
    const float* __restrict__ w1,   const float* __restrict__ b1,
    const float* __restrict__ w2,   const float* __restrict__ b2)
{
    __shared__ __align__(16) float s_gcw[21][24];   // padded rows for float4 LDS
    __shared__ float s_gcb[21];
    __shared__ float s_w1[25 * 45];
    __shared__ float s_b1[25];
    __shared__ float s_w2[45 * 25];
    __shared__ float s_b2[45];
    __shared__ float s_mx[BATCH_PER_BLK][45];
    __shared__ float s_av[BATCH_PER_BLK][45];
    __shared__ float s_hm[BATCH_PER_BLK][25];
    __shared__ float s_ha[BATCH_PER_BLK][25];
    __shared__ float s_lg[BATCH_PER_BLK][45];

    const int tid = threadIdx.x;
    for (int i = tid; i < 441; i += 256) s_gcw[i / 21][i % 21] = gc_w[i];
    for (int i = tid; i < 21;  i += 256) s_gcb[i] = gc_b[i];
    for (int i = tid; i < 1125; i += 256) s_w1[i] = w1[i];
    for (int i = tid; i < 25;  i += 256) s_b1[i] = b1[i];
    for (int i = tid; i < 1125; i += 256) s_w2[i] = w2[i];
    for (int i = tid; i < 45;  i += 256) s_b2[i] = b2[i];
    __syncthreads();

    const int w    = tid >> 5;
    const int lane = tid & 31;
    const int b    = blockIdx.x * BATCH_PER_BLK + w;
    const float* xb = x + (size_t)b * NCL;

    // ---- phase 1: per-channel conv -> max / mean over 21 filters ----
    #pragma unroll
    for (int ci = 0; ci < 2; ci++) {
        const int c = lane + ci * 32;
        if (c < NC) {
            float xr[21];
            #pragma unroll
            for (int m = 0; m < 21; m++) xr[m] = __ldg(xb + c * 21 + m);
            float mx = -1e30f, sv = 0.f;
            #pragma unroll
            for (int o = 0; o < 21; o++) {
                float acc = s_gcb[o];
                #pragma unroll
                for (int k = 0; k < 5; k++) {
                    float4 wv4 = *reinterpret_cast<const float4*>(&s_gcw[o][4 * k]);
                    acc = fmaf(wv4.x, xr[4*k+0], acc);
                    acc = fmaf(wv4.y, xr[4*k+1], acc);
                    acc = fmaf(wv4.z, xr[4*k+2], acc);
                    acc = fmaf(wv4.w, xr[4*k+3], acc);
                }
                acc = fmaf(s_gcw[o][20], xr[20], acc);
                mx = fmaxf(mx, acc);
                sv += acc;
            }
            s_mx[w][c] = mx;
            s_av[w][c] = sv * (1.f / 21.f);
        }
    }
    __syncwarp();

    // ---- phase 2: first MLP layer (25 hidden), shared weights for mx & av ----
    if (lane < 25) {
        float am = s_b1[lane], aa = am;
        #pragma unroll 9
        for (int i = 0; i < 45; i++) {
            const float wv = s_w1[lane * 45 + i];
            am = fmaf(wv, s_mx[w][i], am);
            aa = fmaf(wv, s_av[w][i], aa);
        }
        s_hm[w][lane] = tanhf(am);
        s_ha[w][lane] = tanhf(aa);
    }
    __syncwarp();

    // ---- phase 3: second layer + tanh, summed logits ----
    #pragma unroll
    for (int ci = 0; ci < 2; ci++) {
        const int c = lane + ci * 32;
        if (c < NC) {
            float am = s_b2[c], aa = am;
            #pragma unroll
            for (int j = 0; j < 25; j++) {
                const float wv = s_w2[c * 25 + j];
                am = fmaf(wv, s_hm[w][j], am);
                aa = fmaf(wv, s_ha[w][j], aa);
            }
            s_lg[w][c] = tanhf(am) + tanhf(aa);
        }
    }
    __syncwarp();

    // ---- phase 4: softmax over 45 channels ----
    float mxv = -1e30f;
    #pragma unroll
    for (int c = 0; c < NC; c++) mxv = fmaxf(mxv, s_lg[w][c]);
    float ex[2] = {0.f, 0.f};
    #pragma unroll
    for (int ci = 0; ci < 2; ci++) {
        const int c = lane + ci * 32;
        if (c < NC) ex[ci] = __expf(s_lg[w][c] - mxv);
    }
    __syncwarp();
    #pragma unroll
    for (int ci = 0; ci < 2; ci++) {
        const int c = lane + ci * 32;
        if (c < NC) s_lg[w][c] = ex[ci];
    }
    __syncwarp();
    float sum = 0.f;
    #pragma unroll
    for (int c = 0; c < NC; c++) sum += s_lg[w][c];
    const float inv = 1.f / sum;
    __syncwarp();
    #pragma unroll
    for (int ci = 0; ci < 2; ci++) {
        const int c = lane + ci * 32;
        if (c < NC) {
            const float g = ex[ci] * inv;
            s_lg[w][c] = g;
            g_gate[(size_t)b * NC + c] = g;
        }
    }
    __syncthreads();

    // deterministic per-block partial sum of gate over the 8 batches
    if (tid < NC) {
        float s = 0.f;
        #pragma unroll
        for (int ww = 0; ww < BATCH_PER_BLK; ww++) s += s_lg[ww][tid];
        g_partial[blockIdx.x * NC + tid] = s;
    }
}

// ==================== Kernel B: reduce + top-k + constants ====================
__global__ __launch_bounds__(1024) void topk_kernel(
    const float* __restrict__ wq, const float* __restrict__ bq,
    const float* __restrict__ wk, const float* __restrict__ bk,
    const float* __restrict__ wv, const float* __restrict__ bv,
    const float* __restrict__ wo, const float* __restrict__ bo)
{
    __shared__ float s_sum[NC];
    __shared__ int   s_flag[NC];

    const int tid = threadIdx.x;
    const int c   = tid >> 4;         // 16 threads per channel
    const int sub = tid & 15;

    float s = 0.f;
    if (c < NC) {
        #pragma unroll 8
        for (int blk = sub; blk < NBLK; blk += 16) s += g_partial[blk * NC + c];
    }
    // fixed-order tree reduction within 16-thread group (deterministic)
    #pragma unroll
    for (int off = 8; off > 0; off >>= 1) s += __shfl_down_sync(0xffffffffu, s, off, 16);
    if (c < NC && sub == 0) s_sum[c] = s;
    __syncthreads();

    if (tid < NC) {
        const float v = s_sum[tid];
        int r = 0;
        #pragma unroll
        for (int j = 0; j < NC; j++) {
            const float u = s_sum[j];
            if (u > v || (u == v && j < tid)) r++;
        }
        s_flag[tid] = (r < NE) ? 1 : 0;
    }
    __syncthreads();

    if (tid < NC) {
        if (s_flag[tid]) {
            int pos = 0;
            for (int j = 0; j < tid; j++) pos += s_flag[j];
            g_sel[pos]  = tid;
            g_c2e[tid]  = pos;
        } else {
            g_c2e[tid] = -1;
        }
    }

    if (tid < NE) {
        float a1 = 0.f, a3 = 0.f, c1 = 0.f, c0 = 0.f;
        #pragma unroll
        for (int i = 0; i < 21; i++) {
            const float q  = wq[tid * 21 + i], bqv = bq[tid * 21 + i];
            const float kk = wk[tid * 21 + i];
            const float vv = wv[tid * 21 + i], bvv = bv[tid * 21 + i];
            const float oo = wo[tid * 21 + i];
            a1 = fmaf(q,  kk, a1);
            a3 = fmaf(bqv, kk, a3);
            c1 = fmaf(oo, vv, c1);
            c0 = fmaf(oo, bvv, c0);
        }
        g_a1[tid] = a1; g_a3[tid] = a3; g_c1[tid] = c1; g_c0[tid] = c0 + bo[tid];
    }
}

// ===================== Kernel C: attention + outputs =====================
__global__ __launch_bounds__(256) void attn_kernel(
    const float* __restrict__ x,
    float* __restrict__ outG, float* __restrict__ outA)
{
    __shared__ float s_xs[BATCH_PER_BLK][NPAIR];
    __shared__ float s_y [BATCH_PER_BLK][NPAIR];
    __shared__ float s_g [BATCH_PER_BLK][NE];
    __shared__ float s_a1[NE], s_a3[NE], s_c1[NE], s_c0[NE];
    __shared__ int   s_sel[NE], s_c2e[NC];

    const int tid = threadIdx.x;
    if (tid < NE) {
        s_a1[tid] = g_a1[tid]; s_a3[tid] = g_a3[tid];
        s_c1[tid] = g_c1[tid]; s_c0[tid] = g_c0[tid];
        s_sel[tid] = g_sel[tid];
    }
    if (tid < NC) s_c2e[tid] = g_c2e[tid];
    __syncthreads();

    const int w    = tid >> 5;
    const int lane = tid & 31;
    const int b    = blockIdx.x * BATCH_PER_BLK + w;
    const float* xb = x + (size_t)b * NCL;

    // gather selected channels into shared
    for (int t = lane; t < NPAIR; t += 32) {
        const int e = div21(t);
        const int m = t - e * 21;
        s_xs[w][t] = __ldg(xb + s_sel[e] * 21 + m);
    }
    if (lane < NE) s_g[w][lane] = g_gate[(size_t)b * NC + s_sel[lane]];
    __syncwarp();

    // per-(expert, l) scalar softmax row
    for (int p = lane; p < NPAIR; p += 32) {
        const int e = div21(p);
        const int l = p - e * 21;
        const float* xe = &s_xs[w][e * 21];
        float xr[21];
        #pragma unroll
        for (int m = 0; m < 21; m++) xr[m] = xe[m];
        const float s = fmaf(s_a1[e], xr[l], s_a3[e]);
        float num = 0.f, den = 0.f;
        #pragma unroll
        for (int m = 0; m < 21; m++) {
            const float t2 = __expf(s * xr[m]);
            den += t2;
            num = fmaf(t2, xr[m], num);
        }
        const float y = fmaf(s_c1[e], __fdividef(num, den), s_c0[e]);
        s_y[w][p] = y * s_g[w][e];
    }
    __syncwarp();

    // write full 945-wide rows of G and A (zeros on non-selected channels)
    float* gG = outG + (size_t)b * NCL;
    float* gA = outA + (size_t)b * NCL;
    for (int idx = lane; idx < NCL; idx += 32) {
        const int c = div21(idx);
        const int l = idx - c * 21;
        const int e = s_c2e[c];
        float a = 0.f, g = 0.f;
        if (e >= 0) {
            a = s_y[w][e * 21 + l];
            g = a * s_xs[w][e * 21 + l];
        }
        gG[idx] = g;
        gA[idx] = a;
    }
}

// ================================ launch ================================
extern "C" void kernel_launch(void* const* d_in, const int* in_sizes, int n_in,
                              void* d_out, int out_size)
{
    const float* x    = (const float*)d_in[0];
    const float* gc_w = (const float*)d_in[1];
    const float* gc_b = (const float*)d_in[2];
    const float* w1   = (const float*)d_in[3];
    const float* b1   = (const float*)d_in[4];
    const float* w2   = (const float*)d_in[5];
    const float* b2   = (const float*)d_in[6];
    const float* wq   = (const float*)d_in[7];
    const float* bq   = (const float*)d_in[8];
    const float* wk   = (const float*)d_in[9];
    const float* bk   = (const float*)d_in[10];
    const float* wv   = (const float*)d_in[11];
    const float* bv   = (const float*)d_in[12];
    const float* wo   = (const float*)d_in[13];
    const float* bo   = (const float*)d_in[14];

    float* outG = (float*)d_out;                       // G first
    float* outA = (float*)d_out + (size_t)NB * NCL;    // then A_flat

    gate_kernel<<<NBLK, 256>>>(x, gc_w, gc_b, w1, b1, w2, b2);
    topk_kernel<<<1, 1024>>>(wq, bq, wk, bk, wv, bv, wo, bo);
    attn_kernel<<<NBLK, 256>>>(x, outG, outA);
}